// round 2
// baseline (speedup 1.0000x reference)
#include <cuda_runtime.h>
#include <cstdint>

// Problem constants (fixed by the reference)
#define NN 50000
#define D  128

// Minimal scratch: neighbor counts + dtype flag (keep globals tiny — large
// __device__ arrays trip the harness mem-checkpoint via driver heap growth)
__device__ int g_cnt[NN];
__device__ int g_is64;

// ---------------------------------------------------------------------------
// Detect whether edge_index is int64 or int32.
// True int64: first values are valid node ids in [0, NN).
// int32 pairs reinterpreted as int64: values ~random*2^32 w.h.p.
// ---------------------------------------------------------------------------
__global__ void detect_kernel(const void* __restrict__ idx) {
    if (blockIdx.x == 0 && threadIdx.x == 0) {
        const long long* p = (const long long*)idx;
        int ok = 1;
        #pragma unroll
        for (int i = 0; i < 8; i++) {
            long long v = p[i];
            if (v < 0 || v >= NN) ok = 0;
        }
        g_is64 = ok;
    }
}

// ---------------------------------------------------------------------------
// Zero the accumulator (d_out doubles as the aggregation buffer) + counts
// ---------------------------------------------------------------------------
__global__ void zero_kernel(float4* __restrict__ agg4) {
    int i = blockIdx.x * blockDim.x + threadIdx.x;
    if (i < NN * D / 4) agg4[i] = make_float4(0.f, 0.f, 0.f, 0.f);
    if (i < NN) g_cnt[i] = 0;
}

// ---------------------------------------------------------------------------
// Scatter: one warp per edge. Each lane moves one float4 (32 lanes * 4 = 128).
// Gather x[row] (L2-resident), vector-RED into agg[col], count++.
// ---------------------------------------------------------------------------
__global__ void scatter_kernel(const float4* __restrict__ x4,
                               const void* __restrict__ idx,
                               float* __restrict__ agg, int E) {
    int w    = (blockIdx.x * blockDim.x + threadIdx.x) >> 5;
    int lane = threadIdx.x & 31;
    if (w >= E) return;

    long long r, c;
    if (g_is64) {
        const long long* p = (const long long*)idx;
        r = __ldg(p + w);
        c = __ldg(p + E + w);
    } else {
        const int* p = (const int*)idx;
        r = (long long)__ldg(p + w);
        c = (long long)__ldg(p + E + w);
    }

    float4 v = x4[(size_t)r * (D / 4) + lane];
    float* dst = agg + (size_t)c * D + (size_t)lane * 4;
    asm volatile("red.global.add.v4.f32 [%0], {%1,%2,%3,%4};"
                 :: "l"(dst), "f"(v.x), "f"(v.y), "f"(v.z), "f"(v.w)
                 : "memory");
    if (lane == 0) atomicAdd(g_cnt + c, 1);
}

// ---------------------------------------------------------------------------
// Finalize in place: agg[n] = cnt>0 ? agg[n]/cnt : x[n]
// ---------------------------------------------------------------------------
__global__ void finalize_kernel(const float4* __restrict__ x4,
                                float4* __restrict__ agg4) {
    int i = blockIdx.x * blockDim.x + threadIdx.x;
    if (i >= NN * (D / 4)) return;
    int n = i >> 5;  // D/4 = 32 float4 per row
    int cnt = g_cnt[n];
    if (cnt > 0) {
        float inv = 1.0f / (float)cnt;
        float4 v = agg4[i];
        v.x *= inv; v.y *= inv; v.z *= inv; v.w *= inv;
        agg4[i] = v;
    } else {
        agg4[i] = x4[i];
    }
}

// ---------------------------------------------------------------------------
// In-place SGEMM: out[n][j] = sum_k A[n][k] * W[j][k] + b[j], A == out.
// Safe in place: each block reads only its own 128 rows (all reads in the
// k-loop), then writes those same rows afterwards.
// BM=128, BN=128(=D_OUT), BK=16; 256 threads; 8x8 tile/thread held in 16
// NAMED float4 registers (no local arrays anywhere -> zero stack usage).
// ---------------------------------------------------------------------------
#define SPAD 132  // smem row stride (floats)

#define FMA_ROW(ci0, ci1, av)                                              \
    ci0.x += (av) * b0.x; ci0.y += (av) * b0.y;                            \
    ci0.z += (av) * b0.z; ci0.w += (av) * b0.w;                            \
    ci1.x += (av) * b1.x; ci1.y += (av) * b1.y;                            \
    ci1.z += (av) * b1.z; ci1.w += (av) * b1.w;

__global__ __launch_bounds__(256)
void gemm_kernel(const float* __restrict__ W,
                 const float* __restrict__ bias,
                 float* __restrict__ out, int N) {
    __shared__ float As[16][SPAD];
    __shared__ float Bs[16][SPAD];
    int tid  = threadIdx.x;
    int row0 = blockIdx.x * 128;
    int ty = tid >> 4, tx = tid & 15;

    float4 z = make_float4(0.f, 0.f, 0.f, 0.f);
    float4 c00=z,c01=z, c10=z,c11=z, c20=z,c21=z, c30=z,c31=z;
    float4 c40=z,c41=z, c50=z,c51=z, c60=z,c61=z, c70=z,c71=z;

    #pragma unroll
    for (int k0 = 0; k0 < 128; k0 += 16) {
        // Cooperative load: 512 float4 each for A-tile and W-tile (2/thread)
        #pragma unroll
        for (int it = 0; it < 2; it++) {
            int lin = tid + it * 256;     // 0..511
            int r   = lin >> 2;           // 0..127
            int kq  = lin & 3;            // float4 within 16-wide K slab
            int gr  = row0 + r;
            float4 v = make_float4(0.f, 0.f, 0.f, 0.f);
            if (gr < N) v = *(const float4*)(out + (size_t)gr * 128 + k0 + kq * 4);
            As[kq * 4 + 0][r] = v.x;
            As[kq * 4 + 1][r] = v.y;
            As[kq * 4 + 2][r] = v.z;
            As[kq * 4 + 3][r] = v.w;
            float4 wv = *(const float4*)(W + (size_t)r * 128 + k0 + kq * 4);
            Bs[kq * 4 + 0][r] = wv.x;
            Bs[kq * 4 + 1][r] = wv.y;
            Bs[kq * 4 + 2][r] = wv.z;
            Bs[kq * 4 + 3][r] = wv.w;
        }
        __syncthreads();

        #pragma unroll
        for (int k = 0; k < 16; k++) {
            const float4* ap = (const float4*)&As[k][ty * 8];
            const float4* bp = (const float4*)&Bs[k][tx * 8];
            float4 a0 = ap[0], a1 = ap[1];
            float4 b0 = bp[0], b1 = bp[1];
            FMA_ROW(c00, c01, a0.x)
            FMA_ROW(c10, c11, a0.y)
            FMA_ROW(c20, c21, a0.z)
            FMA_ROW(c30, c31, a0.w)
            FMA_ROW(c40, c41, a1.x)
            FMA_ROW(c50, c51, a1.y)
            FMA_ROW(c60, c61, a1.z)
            FMA_ROW(c70, c71, a1.w)
        }
        __syncthreads();
    }

    float4 bb0 = *(const float4*)(bias + tx * 8);
    float4 bb1 = *(const float4*)(bias + tx * 8 + 4);

    #define STORE_ROW(i, ci0, ci1)                                          \
    {                                                                       \
        int gr = row0 + ty * 8 + (i);                                       \
        if (gr < N) {                                                       \
            float4 o0, o1;                                                  \
            o0.x = ci0.x + bb0.x; o0.y = ci0.y + bb0.y;                     \
            o0.z = ci0.z + bb0.z; o0.w = ci0.w + bb0.w;                     \
            o1.x = ci1.x + bb1.x; o1.y = ci1.y + bb1.y;                     \
            o1.z = ci1.z + bb1.z; o1.w = ci1.w + bb1.w;                     \
            *(float4*)(out + (size_t)gr * 128 + tx * 8)     = o0;           \
            *(float4*)(out + (size_t)gr * 128 + tx * 8 + 4) = o1;           \
        }                                                                   \
    }
    STORE_ROW(0, c00, c01)
    STORE_ROW(1, c10, c11)
    STORE_ROW(2, c20, c21)
    STORE_ROW(3, c30, c31)
    STORE_ROW(4, c40, c41)
    STORE_ROW(5, c50, c51)
    STORE_ROW(6, c60, c61)
    STORE_ROW(7, c70, c71)
    #undef STORE_ROW
}

// ---------------------------------------------------------------------------
extern "C" void kernel_launch(void* const* d_in, const int* in_sizes, int n_in,
                              void* d_out, int out_size) {
    const float* x    = (const float*)d_in[0];
    const void*  idx  = d_in[1];
    const float* W    = (const float*)d_in[2];
    const float* bias = (const float*)d_in[3];
    float* out = (float*)d_out;

    int E = in_sizes[1] / 2;      // 1,600,000 regardless of int32/int64
    int N = in_sizes[0] / D;      // 50,000

    detect_kernel<<<1, 32>>>(idx);

    int zthreads = N * (D / 4);   // 1.6M
    zero_kernel<<<(zthreads + 255) / 256, 256>>>((float4*)out);

    // one warp per edge, 8 warps per 256-thread block
    scatter_kernel<<<(E + 7) / 8, 256>>>((const float4*)x, idx, out, E);

    finalize_kernel<<<(zthreads + 255) / 256, 256>>>((const float4*)x, (float4*)out);

    gemm_kernel<<<(N + 127) / 128, 256>>>(W, bias, out, N);
}

// round 3
// speedup vs baseline: 1.1650x; 1.1650x over previous
#include <cuda_runtime.h>
#include <cstdint>

// Problem constants (fixed by the reference)
#define NN 50000
#define D  128

// Minimal scratch (large __device__ arrays trip the harness mem-checkpoint)
__device__ int g_cnt[NN];
__device__ int g_is64;

// ---------------------------------------------------------------------------
// Detect whether edge_index is int64 or int32.
// ---------------------------------------------------------------------------
__global__ void detect_kernel(const void* __restrict__ idx) {
    if (blockIdx.x == 0 && threadIdx.x == 0) {
        const long long* p = (const long long*)idx;
        int ok = 1;
        #pragma unroll
        for (int i = 0; i < 8; i++) {
            long long v = p[i];
            if (v < 0 || v >= NN) ok = 0;
        }
        g_is64 = ok;
    }
}

// ---------------------------------------------------------------------------
// Zero the accumulator (d_out doubles as aggregation buffer) + counts
// ---------------------------------------------------------------------------
__global__ void zero_kernel(float4* __restrict__ agg4) {
    int i = blockIdx.x * blockDim.x + threadIdx.x;
    if (i < NN * D / 4) agg4[i] = make_float4(0.f, 0.f, 0.f, 0.f);
    if (i < NN) g_cnt[i] = 0;
}

// ---------------------------------------------------------------------------
// Scatter v2: each warp handles 32 edges.
//  - one coalesced index load per lane (edge e = warpBase + lane)
//  - loop j=0..31: shfl-broadcast (r,c), all 32 lanes move one float4 each
//    (512 B gather + 512 B vector-RED per edge, both L2-resident)
//  - count atomic distributed across lanes (lane==j)
// RED has no "memory" clobber so the compiler may hoist the next iteration's
// gather above it (independent edges -> more MLP).
// ---------------------------------------------------------------------------
__global__ __launch_bounds__(256)
void scatter_kernel(const float4* __restrict__ x4,
                    const void* __restrict__ idx,
                    float* __restrict__ agg, int E) {
    int warp = (blockIdx.x * blockDim.x + threadIdx.x) >> 5;
    int lane = threadIdx.x & 31;
    int base = warp * 32;
    if (base >= E) return;

    int e = base + lane;
    int r32 = 0, c32 = 0;
    if (g_is64) {
        const long long* p = (const long long*)idx;
        if (e < E) { r32 = (int)__ldg(p + e); c32 = (int)__ldg(p + E + e); }
    } else {
        const int* p = (const int*)idx;
        if (e < E) { r32 = __ldg(p + e); c32 = __ldg(p + E + e); }
    }

    int nE = E - base; if (nE > 32) nE = 32;
    #pragma unroll 4
    for (int j = 0; j < nE; j++) {
        int r = __shfl_sync(0xffffffffu, r32, j);
        int c = __shfl_sync(0xffffffffu, c32, j);
        float4 v = __ldg(x4 + (size_t)r * (D / 4) + lane);
        float* dst = agg + (size_t)c * D + (size_t)lane * 4;
        asm volatile("red.global.add.v4.f32 [%0], {%1,%2,%3,%4};"
                     :: "l"(dst), "f"(v.x), "f"(v.y), "f"(v.z), "f"(v.w));
        if (lane == j) atomicAdd(g_cnt + c, 1);
    }
}

// ---------------------------------------------------------------------------
// In-place SGEMM with fused mean/fallback:
//   A[n] = cnt[n]>0 ? agg[n]/cnt[n] : x[n]   (applied during smem fill)
//   out[n][j] = sum_k A[n][k] * W[j][k] + b[j],  A(agg) == out (in place).
// Safe in place: each block reads only its own 128 rows, all reads precede
// all writes. Row index per (thread,it) is k0-invariant, so scale/src are
// hoisted before the k-loop.
// BM=128, BN=128, BK=16; 256 threads; 8x8 tile/thread in named float4 regs.
// ---------------------------------------------------------------------------
#define SPAD 132

#define FMA_ROW(ci0, ci1, av)                                              \
    ci0.x += (av) * b0.x; ci0.y += (av) * b0.y;                            \
    ci0.z += (av) * b0.z; ci0.w += (av) * b0.w;                            \
    ci1.x += (av) * b1.x; ci1.y += (av) * b1.y;                            \
    ci1.z += (av) * b1.z; ci1.w += (av) * b1.w;

__global__ __launch_bounds__(256)
void gemm_kernel(const float* __restrict__ x,
                 const float* __restrict__ W,
                 const float* __restrict__ bias,
                 float* __restrict__ out, int N) {
    __shared__ float As[16][SPAD];
    __shared__ float Bs[16][SPAD];
    int tid  = threadIdx.x;
    int row0 = blockIdx.x * 128;
    int ty = tid >> 4, tx = tid & 15;

    // k0-invariant A-load rows for this thread (it = 0, 1)
    int r0 = tid >> 2;            // 0..63
    int r1 = (tid + 256) >> 2;    // 64..127
    int kq = tid & 3;
    int gr0 = row0 + r0, gr1 = row0 + r1;

    const float* src0 = out; float s0 = 1.0f; bool ok0 = (gr0 < N);
    const float* src1 = out; float s1 = 1.0f; bool ok1 = (gr1 < N);
    if (ok0) { int c = g_cnt[gr0]; if (c > 0) s0 = 1.0f / (float)c; else src0 = x; }
    if (ok1) { int c = g_cnt[gr1]; if (c > 0) s1 = 1.0f / (float)c; else src1 = x; }

    float4 z = make_float4(0.f, 0.f, 0.f, 0.f);
    float4 c00=z,c01=z, c10=z,c11=z, c20=z,c21=z, c30=z,c31=z;
    float4 c40=z,c41=z, c50=z,c51=z, c60=z,c61=z, c70=z,c71=z;

    #pragma unroll
    for (int k0 = 0; k0 < 128; k0 += 16) {
        // A tile (scaled / fallback applied here)
        {
            float4 v = z;
            if (ok0) v = *(const float4*)(src0 + (size_t)gr0 * 128 + k0 + kq * 4);
            As[kq * 4 + 0][r0] = v.x * s0;
            As[kq * 4 + 1][r0] = v.y * s0;
            As[kq * 4 + 2][r0] = v.z * s0;
            As[kq * 4 + 3][r0] = v.w * s0;
            float4 u = z;
            if (ok1) u = *(const float4*)(src1 + (size_t)gr1 * 128 + k0 + kq * 4);
            As[kq * 4 + 0][r1] = u.x * s1;
            As[kq * 4 + 1][r1] = u.y * s1;
            As[kq * 4 + 2][r1] = u.z * s1;
            As[kq * 4 + 3][r1] = u.w * s1;
        }
        // W tile
        #pragma unroll
        for (int it = 0; it < 2; it++) {
            int lin = tid + it * 256;
            int r   = lin >> 2;
            int kw  = lin & 3;
            float4 wv = *(const float4*)(W + (size_t)r * 128 + k0 + kw * 4);
            Bs[kw * 4 + 0][r] = wv.x;
            Bs[kw * 4 + 1][r] = wv.y;
            Bs[kw * 4 + 2][r] = wv.z;
            Bs[kw * 4 + 3][r] = wv.w;
        }
        __syncthreads();

        #pragma unroll
        for (int k = 0; k < 16; k++) {
            const float4* ap = (const float4*)&As[k][ty * 8];
            const float4* bp = (const float4*)&Bs[k][tx * 8];
            float4 a0 = ap[0], a1 = ap[1];
            float4 b0 = bp[0], b1 = bp[1];
            FMA_ROW(c00, c01, a0.x)
            FMA_ROW(c10, c11, a0.y)
            FMA_ROW(c20, c21, a0.z)
            FMA_ROW(c30, c31, a0.w)
            FMA_ROW(c40, c41, a1.x)
            FMA_ROW(c50, c51, a1.y)
            FMA_ROW(c60, c61, a1.z)
            FMA_ROW(c70, c71, a1.w)
        }
        __syncthreads();
    }

    float4 bb0 = *(const float4*)(bias + tx * 8);
    float4 bb1 = *(const float4*)(bias + tx * 8 + 4);

    #define STORE_ROW(i, ci0, ci1)                                          \
    {                                                                       \
        int gr = row0 + ty * 8 + (i);                                       \
        if (gr < N) {                                                       \
            float4 o0, o1;                                                  \
            o0.x = ci0.x + bb0.x; o0.y = ci0.y + bb0.y;                     \
            o0.z = ci0.z + bb0.z; o0.w = ci0.w + bb0.w;                     \
            o1.x = ci1.x + bb1.x; o1.y = ci1.y + bb1.y;                     \
            o1.z = ci1.z + bb1.z; o1.w = ci1.w + bb1.w;                     \
            *(float4*)(out + (size_t)gr * 128 + tx * 8)     = o0;           \
            *(float4*)(out + (size_t)gr * 128 + tx * 8 + 4) = o1;           \
        }                                                                   \
    }
    STORE_ROW(0, c00, c01)
    STORE_ROW(1, c10, c11)
    STORE_ROW(2, c20, c21)
    STORE_ROW(3, c30, c31)
    STORE_ROW(4, c40, c41)
    STORE_ROW(5, c50, c51)
    STORE_ROW(6, c60, c61)
    STORE_ROW(7, c70, c71)
    #undef STORE_ROW
}

// ---------------------------------------------------------------------------
extern "C" void kernel_launch(void* const* d_in, const int* in_sizes, int n_in,
                              void* d_out, int out_size) {
    const float* x    = (const float*)d_in[0];
    const void*  idx  = d_in[1];
    const float* W    = (const float*)d_in[2];
    const float* bias = (const float*)d_in[3];
    float* out = (float*)d_out;

    int E = in_sizes[1] / 2;      // 1,600,000 regardless of int32/int64
    int N = in_sizes[0] / D;      // 50,000

    detect_kernel<<<1, 32>>>(idx);

    int zthreads = N * (D / 4);
    zero_kernel<<<(zthreads + 255) / 256, 256>>>((float4*)out);

    // 32 edges per warp, 8 warps per 256-thread block => 256 edges per block
    scatter_kernel<<<(E + 255) / 256, 256>>>((const float4*)x, idx, out, E);

    gemm_kernel<<<(N + 127) / 128, 256>>>(x, W, bias, out, N);
}

// round 5
// speedup vs baseline: 1.4153x; 1.2148x over previous
#include <cuda_runtime.h>
#include <cstdint>

// Problem constants (fixed by the reference)
#define NN 50000
#define D  128

// Minimal scratch (large __device__ arrays trip the harness mem-checkpoint)
__device__ int g_cnt[NN];
__device__ int g_is64;

// ---------------------------------------------------------------------------
// Detect whether edge_index is int64 or int32.
// ---------------------------------------------------------------------------
__global__ void detect_kernel(const void* __restrict__ idx) {
    if (blockIdx.x == 0 && threadIdx.x == 0) {
        const long long* p = (const long long*)idx;
        int ok = 1;
        #pragma unroll
        for (int i = 0; i < 8; i++) {
            long long v = p[i];
            if (v < 0 || v >= NN) ok = 0;
        }
        g_is64 = ok;
    }
}

// ---------------------------------------------------------------------------
// Zero the accumulator (d_out doubles as aggregation buffer) + counts
// ---------------------------------------------------------------------------
__global__ void zero_kernel(float4* __restrict__ agg4) {
    int i = blockIdx.x * blockDim.x + threadIdx.x;
    if (i < NN * D / 4) agg4[i] = make_float4(0.f, 0.f, 0.f, 0.f);
    if (i < NN) g_cnt[i] = 0;
}

// ---------------------------------------------------------------------------
// Scatter: each warp handles 32 edges (coalesced index loads + shfl bcast).
// 512 B gather + 512 B vector-RED per edge, both L2-resident.
// ---------------------------------------------------------------------------
__global__ __launch_bounds__(256)
void scatter_kernel(const float4* __restrict__ x4,
                    const void* __restrict__ idx,
                    float* __restrict__ agg, int E) {
    int warp = (blockIdx.x * blockDim.x + threadIdx.x) >> 5;
    int lane = threadIdx.x & 31;
    int base = warp * 32;
    if (base >= E) return;

    int e = base + lane;
    int r32 = 0, c32 = 0;
    if (g_is64) {
        const long long* p = (const long long*)idx;
        if (e < E) { r32 = (int)__ldg(p + e); c32 = (int)__ldg(p + E + e); }
    } else {
        const int* p = (const int*)idx;
        if (e < E) { r32 = __ldg(p + e); c32 = __ldg(p + E + e); }
    }

    int nE = E - base; if (nE > 32) nE = 32;
    #pragma unroll 4
    for (int j = 0; j < nE; j++) {
        int r = __shfl_sync(0xffffffffu, r32, j);
        int c = __shfl_sync(0xffffffffu, c32, j);
        float4 v = __ldg(x4 + (size_t)r * (D / 4) + lane);
        float* dst = agg + (size_t)c * D + (size_t)lane * 4;
        asm volatile("red.global.add.v4.f32 [%0], {%1,%2,%3,%4};"
                     :: "l"(dst), "f"(v.x), "f"(v.y), "f"(v.z), "f"(v.w));
        if (lane == j) atomicAdd(g_cnt + c, 1);
    }
}

// ---------------------------------------------------------------------------
// tf32 tensor-core GEMM, in place, with fused mean / isolated-node fallback:
//   A[n] = cnt[n]>0 ? agg[n]/cnt[n] : x[n]   (applied + cvt.rna.tf32 at load)
//   out[n][j] = sum_k A[n][k] * W[j][k] + b[j],  A(agg) == out.
// BM=128, BN=128, K=128, BK=16 smem slabs; 256 threads = 8 warps in a 2x4
// grid; each warp owns a 64x32 output patch = 4x4 m16n8k8 tiles.
// smem layouts: As[k][m], Ws[k][n]  (n-th row of W = B[k][n] after transpose)
// exactly match the tf32 fragment feed.
// In-place safe: block reads only its own 128 rows; all reads precede writes.
// ---------------------------------------------------------------------------
#define SPAD 132

__device__ __forceinline__ uint32_t f2tf32(float v) {
    uint32_t u;
    asm("cvt.rna.tf32.f32 %0, %1;" : "=r"(u) : "f"(v));
    return u;
}

__global__ __launch_bounds__(256)
void gemm_kernel(const float* __restrict__ x,
                 const float* __restrict__ W,
                 const float* __restrict__ bias,
                 float* __restrict__ out, int N) {
    __shared__ uint32_t As[16][SPAD];
    __shared__ uint32_t Ws[16][SPAD];
    int tid  = threadIdx.x;
    int row0 = blockIdx.x * 128;
    int wid  = tid >> 5;
    int lane = tid & 31;
    int g    = lane >> 2;      // fragment group id (0..7)
    int c4   = lane & 3;       // fragment lane-in-group (0..3)
    int wy   = wid >> 2;       // 0..1 -> 64 rows each
    int wx   = wid & 3;        // 0..3 -> 32 cols each

    // k0-invariant A-load rows for this thread
    int r0 = tid >> 2;            // 0..63
    int r1 = r0 + 64;             // 64..127
    int kq = tid & 3;
    int gr0 = row0 + r0, gr1 = row0 + r1;

    const float* src0 = out; float s0 = 1.0f; bool ok0 = (gr0 < N);
    const float* src1 = out; float s1 = 1.0f; bool ok1 = (gr1 < N);
    if (ok0) { int cc = g_cnt[gr0]; if (cc > 0) s0 = 1.0f / (float)cc; else src0 = x; }
    if (ok1) { int cc = g_cnt[gr1]; if (cc > 0) s1 = 1.0f / (float)cc; else src1 = x; }

    float acc[4][4][4];   // [rowtile i][coltile j][frag reg]
    #pragma unroll
    for (int i = 0; i < 4; i++)
        #pragma unroll
        for (int j = 0; j < 4; j++)
            #pragma unroll
            for (int q = 0; q < 4; q++) acc[i][j][q] = 0.f;

    for (int k0 = 0; k0 < 128; k0 += 16) {
        // ---- A tile (scale / fallback + tf32 convert) ----
        {
            float4 v = make_float4(0.f, 0.f, 0.f, 0.f);
            if (ok0) v = *(const float4*)(src0 + (size_t)gr0 * 128 + k0 + kq * 4);
            As[kq * 4 + 0][r0] = f2tf32(v.x * s0);
            As[kq * 4 + 1][r0] = f2tf32(v.y * s0);
            As[kq * 4 + 2][r0] = f2tf32(v.z * s0);
            As[kq * 4 + 3][r0] = f2tf32(v.w * s0);
            float4 u = make_float4(0.f, 0.f, 0.f, 0.f);
            if (ok1) u = *(const float4*)(src1 + (size_t)gr1 * 128 + k0 + kq * 4);
            As[kq * 4 + 0][r1] = f2tf32(u.x * s1);
            As[kq * 4 + 1][r1] = f2tf32(u.y * s1);
            As[kq * 4 + 2][r1] = f2tf32(u.z * s1);
            As[kq * 4 + 3][r1] = f2tf32(u.w * s1);
        }
        // ---- W tile transposed: Ws[k][n] = W[n][k] ----
        #pragma unroll
        for (int it = 0; it < 2; it++) {
            int lin = tid + it * 256;
            int r   = lin >> 2;       // output col n
            int kw  = lin & 3;
            float4 wv = *(const float4*)(W + (size_t)r * 128 + k0 + kw * 4);
            Ws[kw * 4 + 0][r] = f2tf32(wv.x);
            Ws[kw * 4 + 1][r] = f2tf32(wv.y);
            Ws[kw * 4 + 2][r] = f2tf32(wv.z);
            Ws[kw * 4 + 3][r] = f2tf32(wv.w);
        }
        __syncthreads();

        #pragma unroll
        for (int ks = 0; ks < 16; ks += 8) {
            // B fragments for the 4 col-tiles
            uint32_t bf[4][2];
            #pragma unroll
            for (int j = 0; j < 4; j++) {
                int n0 = wx * 32 + j * 8;
                bf[j][0] = Ws[ks + c4][n0 + g];
                bf[j][1] = Ws[ks + c4 + 4][n0 + g];
            }
            // A fragments for the 4 row-tiles, then mma across col-tiles
            #pragma unroll
            for (int i = 0; i < 4; i++) {
                int m0 = wy * 64 + i * 16;
                uint32_t a0 = As[ks + c4][m0 + g];
                uint32_t a1 = As[ks + c4][m0 + g + 8];
                uint32_t a2 = As[ks + c4 + 4][m0 + g];
                uint32_t a3 = As[ks + c4 + 4][m0 + g + 8];
                #pragma unroll
                for (int j = 0; j < 4; j++) {
                    asm volatile(
                        "mma.sync.aligned.m16n8k8.row.col.f32.tf32.tf32.f32 "
                        "{%0,%1,%2,%3}, {%4,%5,%6,%7}, {%8,%9}, {%0,%1,%2,%3};"
                        : "+f"(acc[i][j][0]), "+f"(acc[i][j][1]),
                          "+f"(acc[i][j][2]), "+f"(acc[i][j][3])
                        : "r"(a0), "r"(a1), "r"(a2), "r"(a3),
                          "r"(bf[j][0]), "r"(bf[j][1]));
                }
            }
        }
        __syncthreads();
    }

    // ---- epilogue: bias + store (float2 per c-pair) ----
    #pragma unroll
    for (int j = 0; j < 4; j++) {
        int n = wx * 32 + j * 8 + 2 * c4;
        float2 bb = *(const float2*)(bias + n);
        #pragma unroll
        for (int i = 0; i < 4; i++) {
            int mr = row0 + wy * 64 + i * 16 + g;
            if (mr < N) {
                float2 o;
                o.x = acc[i][j][0] + bb.x;
                o.y = acc[i][j][1] + bb.y;
                *(float2*)(out + (size_t)mr * 128 + n) = o;
            }
            int mr2 = mr + 8;
            if (mr2 < N) {
                float2 o;
                o.x = acc[i][j][2] + bb.x;
                o.y = acc[i][j][3] + bb.y;
                *(float2*)(out + (size_t)mr2 * 128 + n) = o;
            }
        }
    }
}

// ---------------------------------------------------------------------------
extern "C" void kernel_launch(void* const* d_in, const int* in_sizes, int n_in,
                              void* d_out, int out_size) {
    const float* x    = (const float*)d_in[0];
    const void*  idx  = d_in[1];
    const float* W    = (const float*)d_in[2];
    const float* bias = (const float*)d_in[3];
    float* out = (float*)d_out;

    int E = in_sizes[1] / 2;      // 1,600,000 regardless of int32/int64
    int N = in_sizes[0] / D;      // 50,000

    detect_kernel<<<1, 32>>>(idx);

    int zthreads = N * (D / 4);
    zero_kernel<<<(zthreads + 255) / 256, 256>>>((float4*)out);

    scatter_kernel<<<(E + 255) / 256, 256>>>((const float4*)x, idx, out, E);

    gemm_kernel<<<(N + 127) / 128, 256>>>(x, W, bias, out, N);
}